// round 2
// baseline (speedup 1.0000x reference)
#include <cuda_runtime.h>
#include <cstdint>
#include <cstddef>

// Problem constants
#define NUQ 100000
#define NIQ 100000
#define DD 128
#define NSS 5
#define EE 500000
#define NSEG (NSS * NUQ)          // 500000 segments per side
#define NEDGE (NSS * EE)          // 2500000 edges per side
#define KTOT (NSS * DD)           // 640
#define TSEG (2 * NSEG)           // 1000000 total segments
#define TEDGE (2 * NEDGE)         // 5000000 total edges

// ---------------- static scratch (device globals; no allocation) -----------
__device__ float g_Wc[KTOT * DD];                    // stacked cumulative weights [640][128]
__device__ float g_Pu[(size_t)NUQ * KTOT];           // P user side  [NU][640]
__device__ float g_Pi[(size_t)NIQ * KTOT];           // P item side  [NI][640]
__device__ int   g_cnt[TSEG];                        // per-segment edge counts
__device__ int   g_rp[TSEG + 1];                     // CSR row pointers (joint over both sides)
__device__ int   g_cur[TSEG];                        // scatter cursors
__device__ int   g_ecol[TEDGE];                      // CSR cols
__device__ float g_eval[TEDGE];                      // CSR vals
__device__ int   g_bsum[1024];                       // scan block sums

// ---------------- cumulative weight stack ----------------------------------
// weight layout: (DIN, DOUT, NS) row-major -> idx = din*DOUT*NS + dout*NS + s
// g_Wc[(s*128 + din)*128 + dout] = sum_{j<=s} weight[din][dout][j]
__global__ void k_wc(const float* __restrict__ w) {
    int din = blockIdx.x;     // 128
    int dout = threadIdx.x;   // 128
    float acc = 0.f;
#pragma unroll
    for (int s = 0; s < NSS; s++) {
        acc += w[din * (DD * NSS) + dout * NSS + s];
        g_Wc[((size_t)(s * DD + din)) * DD + dout] = acc;
    }
}

// ---------------- CSR build -------------------------------------------------
__global__ void k_zero_counts() {
    for (int i = blockIdx.x * blockDim.x + threadIdx.x; i < TSEG;
         i += gridDim.x * blockDim.x)
        g_cnt[i] = 0;
}

__global__ void k_hist(const int* __restrict__ urows, const int* __restrict__ irows) {
    for (int i = blockIdx.x * blockDim.x + threadIdx.x; i < TEDGE;
         i += gridDim.x * blockDim.x) {
        int side = (i >= NEDGE);
        int e = i - side * NEDGE;
        const int* rows = side ? irows : urows;
        int s = e / EE;
        int r = rows[e];
        atomicAdd(&g_cnt[side * NSEG + s * NUQ + r], 1);
    }
}

// exclusive scan over g_cnt[TSEG] -> g_rp, 2-level (1024 per block)
__global__ void k_scan1() {
    __shared__ int sh[1024];
    int tid = threadIdx.x;
    int i = blockIdx.x * 1024 + tid;
    int v = (i < TSEG) ? g_cnt[i] : 0;
    sh[tid] = v;
    __syncthreads();
    for (int off = 1; off < 1024; off <<= 1) {
        int t = (tid >= off) ? sh[tid - off] : 0;
        __syncthreads();
        sh[tid] += t;
        __syncthreads();
    }
    if (i < TSEG) g_rp[i] = sh[tid] - v;   // local exclusive
    if (tid == 1023) g_bsum[blockIdx.x] = sh[1023];
}

__global__ void k_scan2(int nb) {
    __shared__ int sh[1024];
    int tid = threadIdx.x;
    int v = (tid < nb) ? g_bsum[tid] : 0;
    sh[tid] = v;
    __syncthreads();
    for (int off = 1; off < 1024; off <<= 1) {
        int t = (tid >= off) ? sh[tid - off] : 0;
        __syncthreads();
        sh[tid] += t;
        __syncthreads();
    }
    if (tid < nb) g_bsum[tid] = sh[tid] - v;  // exclusive block offsets
}

__global__ void k_scan3() {
    int i = blockIdx.x * 1024 + threadIdx.x;
    if (i < TSEG) {
        int v = g_rp[i] + g_bsum[blockIdx.x];
        g_rp[i] = v;
        g_cur[i] = v;
    }
    if (i == 0) g_rp[TSEG] = TEDGE;
}

__global__ void k_scatter(const int* __restrict__ urows, const int* __restrict__ ucols,
                          const float* __restrict__ uvals,
                          const int* __restrict__ irows, const int* __restrict__ icols,
                          const float* __restrict__ ivals) {
    for (int i = blockIdx.x * blockDim.x + threadIdx.x; i < TEDGE;
         i += gridDim.x * blockDim.x) {
        int side = (i >= NEDGE);
        int e = i - side * NEDGE;
        const int* rows = side ? irows : urows;
        const int* cols = side ? icols : ucols;
        const float* vals = side ? ivals : uvals;
        int s = e / EE;
        int seg = side * NSEG + s * NUQ + rows[e];
        int p = atomicAdd(&g_cur[seg], 1);
        g_ecol[p] = cols[e];
        g_eval[p] = vals[e];
    }
}

// ---------------- SPMM: one warp per segment --------------------------------
// user side gathers item_inputs, item side gathers user_inputs
__global__ void __launch_bounds__(256) k_spmm(const float* __restrict__ uin,
                                              const float* __restrict__ iin) {
    int gw = (blockIdx.x * blockDim.x + threadIdx.x) >> 5;
    int lane = threadIdx.x & 31;
    if (gw >= TSEG) return;
    int side = (gw >= NSEG);
    int seg = gw - side * NSEG;
    const float* dense = side ? uin : iin;
    int s = seg / NUQ;
    int r = seg - s * NUQ;
    int b = g_rp[gw];
    int en = g_rp[gw + 1];
    float4 acc = make_float4(0.f, 0.f, 0.f, 0.f);
    for (int e = b; e < en; e++) {
        int c = g_ecol[e];
        float v = g_eval[e];
        float4 x = __ldg(((const float4*)(dense + (size_t)c * DD)) + lane);
        acc.x += v * x.x;
        acc.y += v * x.y;
        acc.z += v * x.z;
        acc.w += v * x.w;
    }
    float* P = side ? g_Pi : g_Pu;
    ((float4*)(P + (size_t)r * KTOT + s * DD))[lane] = acc;
}

// ---------------- GEMM + ReLU:  out = relu(P[1e5,640] @ Wc[640,128]) -------
// 128x128 block tile, BK=8, 256 threads, 8x8 microtile
#define BM 128
#define BN 128
#define BK 8
__global__ void __launch_bounds__(256) k_gemm_relu(float* __restrict__ out) {
    const float* __restrict__ A = blockIdx.y ? g_Pi : g_Pu;
    float* __restrict__ C = out + (size_t)blockIdx.y * NUQ * DD;
    int mbase = blockIdx.x * BM;

    __shared__ float As[BK][BM];
    __shared__ float Bs[BK][BN];

    int tid = threadIdx.x;
    int arow = tid >> 1;                 // 0..127
    int ak4 = (tid & 1) * 4;             // 0 or 4
    int brow = tid >> 5;                 // 0..7
    int bcol4 = (tid & 31) * 4;          // 0..124
    int tx = tid & 15;                   // 0..15
    int ty = tid >> 4;                   // 0..15

    float acc[8][8];
#pragma unroll
    for (int i = 0; i < 8; i++)
#pragma unroll
        for (int j = 0; j < 8; j++) acc[i][j] = 0.f;

    int grow = mbase + arow;
    const float* Arow = A + (size_t)grow * KTOT;

    for (int kt = 0; kt < KTOT; kt += BK) {
        float4 av = make_float4(0.f, 0.f, 0.f, 0.f);
        if (grow < NUQ) av = *(const float4*)(Arow + kt + ak4);
        As[ak4 + 0][arow] = av.x;
        As[ak4 + 1][arow] = av.y;
        As[ak4 + 2][arow] = av.z;
        As[ak4 + 3][arow] = av.w;

        float4 bv = *(const float4*)(g_Wc + (size_t)(kt + brow) * DD + bcol4);
        *(float4*)&Bs[brow][bcol4] = bv;
        __syncthreads();

#pragma unroll
        for (int k = 0; k < BK; k++) {
            float ra[8], rb[8];
#pragma unroll
            for (int j = 0; j < 8; j++) ra[j] = As[k][ty * 8 + j];
#pragma unroll
            for (int j = 0; j < 8; j++) rb[j] = Bs[k][tx * 8 + j];
#pragma unroll
            for (int i = 0; i < 8; i++)
#pragma unroll
                for (int j = 0; j < 8; j++) acc[i][j] += ra[i] * rb[j];
        }
        __syncthreads();
    }

#pragma unroll
    for (int i = 0; i < 8; i++) {
        int r = mbase + ty * 8 + i;
        if (r < NUQ) {
            float4 o0, o1;
            o0.x = fmaxf(acc[i][0], 0.f);
            o0.y = fmaxf(acc[i][1], 0.f);
            o0.z = fmaxf(acc[i][2], 0.f);
            o0.w = fmaxf(acc[i][3], 0.f);
            o1.x = fmaxf(acc[i][4], 0.f);
            o1.y = fmaxf(acc[i][5], 0.f);
            o1.z = fmaxf(acc[i][6], 0.f);
            o1.w = fmaxf(acc[i][7], 0.f);
            *(float4*)(C + (size_t)r * DD + tx * 8) = o0;
            *(float4*)(C + (size_t)r * DD + tx * 8 + 4) = o1;
        }
    }
}

// ---------------- launcher --------------------------------------------------
extern "C" void kernel_launch(void* const* d_in, const int* in_sizes, int n_in,
                              void* d_out, int out_size) {
    const float* uin   = (const float*)d_in[0];   // user_inputs  [NU,128]
    const float* iin   = (const float*)d_in[1];   // item_inputs  [NI,128]
    const float* w     = (const float*)d_in[2];   // weight       [128,128,5]
    const int*   urows = (const int*)d_in[3];     // u_rows [5,E]
    const int*   ucols = (const int*)d_in[4];
    const float* uvals = (const float*)d_in[5];
    const int*   irows = (const int*)d_in[6];
    const int*   icols = (const int*)d_in[7];
    const float* ivals = (const float*)d_in[8];
    float* out = (float*)d_out;                   // [2*NU*128]: user then item

    (void)in_sizes; (void)n_in; (void)out_size;

    // 1. cumulative weight stack
    k_wc<<<DD, DD>>>(w);

    // 2. CSR build
    k_zero_counts<<<2048, 256>>>();
    k_hist<<<4096, 256>>>(urows, irows);
    int nblk = (TSEG + 1023) / 1024;   // 977
    k_scan1<<<nblk, 1024>>>();
    k_scan2<<<1, 1024>>>(nblk);
    k_scan3<<<nblk, 1024>>>();
    k_scatter<<<4096, 256>>>(urows, ucols, uvals, irows, icols, ivals);

    // 3. SPMM on raw inputs -> P matrices [*,640]
    int spmm_blocks = (TSEG * 32 + 255) / 256;    // 125000
    k_spmm<<<spmm_blocks, 256>>>(uin, iin);

    // 4. fused GEMM (K=640) + ReLU -> output
    dim3 ggrid((NUQ + BM - 1) / BM, 2);
    k_gemm_relu<<<ggrid, 256>>>(out);
}

// round 4
// speedup vs baseline: 1.8823x; 1.8823x over previous
#include <cuda_runtime.h>
#include <cstdint>
#include <cstddef>

// Problem constants
#define NUQ 100000
#define NIQ 100000
#define DD 128
#define NSS 5
#define EE 500000
#define NSEG (NSS * NUQ)          // 500000 segments per side
#define NEDGE (NSS * EE)          // 2500000 edges per side
#define KTOT (NSS * DD)           // 640
#define TSEG (2 * NSEG)           // 1000000 total segments
#define TEDGE (2 * NEDGE)         // 5000000 total edges
#define GM (2 * NUQ)              // 200000 GEMM rows (user block then item block)

// ---------------- static scratch (device globals; no allocation) -----------
__device__ float g_Wc[KTOT * DD];                    // stacked cumulative weights [640][128] (tf32-rounded)
__device__ float g_P[(size_t)GM * KTOT];             // P matrix [200000][640] (tf32-rounded)
__device__ int   g_cnt[TSEG];                        // per-segment edge counts
__device__ int   g_rp[TSEG + 1];                     // CSR row pointers (joint over both sides)
__device__ int   g_cur[TSEG];                        // scatter cursors
__device__ int   g_ecol[TEDGE];                      // CSR cols
__device__ float g_eval[TEDGE];                      // CSR vals
__device__ int   g_bsum[1024];                       // scan block sums

__device__ __forceinline__ float tf32_rna(float x) {
    unsigned u;
    asm("cvt.rna.tf32.f32 %0, %1;" : "=r"(u) : "f"(x));
    return __uint_as_float(u);
}

// ---------------- cumulative weight stack ----------------------------------
// weight layout: (DIN, DOUT, NS) row-major -> idx = din*DOUT*NS + dout*NS + s
// g_Wc[(s*128 + din)*128 + dout] = tf32( sum_{j<=s} weight[din][dout][j] )
__global__ void k_wc(const float* __restrict__ w) {
    int din = blockIdx.x;     // 128
    int dout = threadIdx.x;   // 128
    float acc = 0.f;
#pragma unroll
    for (int s = 0; s < NSS; s++) {
        acc += w[din * (DD * NSS) + dout * NSS + s];
        g_Wc[((size_t)(s * DD + din)) * DD + dout] = tf32_rna(acc);
    }
}

// ---------------- CSR build -------------------------------------------------
__global__ void k_zero_counts() {
    for (int i = blockIdx.x * blockDim.x + threadIdx.x; i < TSEG;
         i += gridDim.x * blockDim.x)
        g_cnt[i] = 0;
}

__global__ void k_hist(const int* __restrict__ urows, const int* __restrict__ irows) {
    for (int i = blockIdx.x * blockDim.x + threadIdx.x; i < TEDGE;
         i += gridDim.x * blockDim.x) {
        int side = (i >= NEDGE);
        int e = i - side * NEDGE;
        const int* rows = side ? irows : urows;
        int s = e / EE;
        int r = rows[e];
        atomicAdd(&g_cnt[side * NSEG + s * NUQ + r], 1);
    }
}

__global__ void k_scan1() {
    __shared__ int sh[1024];
    int tid = threadIdx.x;
    int i = blockIdx.x * 1024 + tid;
    int v = (i < TSEG) ? g_cnt[i] : 0;
    sh[tid] = v;
    __syncthreads();
    for (int off = 1; off < 1024; off <<= 1) {
        int t = (tid >= off) ? sh[tid - off] : 0;
        __syncthreads();
        sh[tid] += t;
        __syncthreads();
    }
    if (i < TSEG) g_rp[i] = sh[tid] - v;   // local exclusive
    if (tid == 1023) g_bsum[blockIdx.x] = sh[1023];
}

__global__ void k_scan2(int nb) {
    __shared__ int sh[1024];
    int tid = threadIdx.x;
    int v = (tid < nb) ? g_bsum[tid] : 0;
    sh[tid] = v;
    __syncthreads();
    for (int off = 1; off < 1024; off <<= 1) {
        int t = (tid >= off) ? sh[tid - off] : 0;
        __syncthreads();
        sh[tid] += t;
        __syncthreads();
    }
    if (tid < nb) g_bsum[tid] = sh[tid] - v;  // exclusive block offsets
}

__global__ void k_scan3() {
    int i = blockIdx.x * 1024 + threadIdx.x;
    if (i < TSEG) {
        int v = g_rp[i] + g_bsum[blockIdx.x];
        g_rp[i] = v;
        g_cur[i] = v;
    }
    if (i == 0) g_rp[TSEG] = TEDGE;
}

__global__ void k_scatter(const int* __restrict__ urows, const int* __restrict__ ucols,
                          const float* __restrict__ uvals,
                          const int* __restrict__ irows, const int* __restrict__ icols,
                          const float* __restrict__ ivals) {
    for (int i = blockIdx.x * blockDim.x + threadIdx.x; i < TEDGE;
         i += gridDim.x * blockDim.x) {
        int side = (i >= NEDGE);
        int e = i - side * NEDGE;
        const int* rows = side ? irows : urows;
        const int* cols = side ? icols : ucols;
        const float* vals = side ? ivals : uvals;
        int s = e / EE;
        int seg = side * NSEG + s * NUQ + rows[e];
        int p = atomicAdd(&g_cur[seg], 1);
        g_ecol[p] = cols[e];
        g_eval[p] = vals[e];
    }
}

// ---------------- SPMM: one warp per segment --------------------------------
// user side gathers item_inputs, item side gathers user_inputs.
// Writes tf32-rounded values to g_P so the tensor-core GEMM needs no converts.
__global__ void __launch_bounds__(256) k_spmm(const float* __restrict__ uin,
                                              const float* __restrict__ iin) {
    int gw = (blockIdx.x * blockDim.x + threadIdx.x) >> 5;
    int lane = threadIdx.x & 31;
    if (gw >= TSEG) return;
    int side = (gw >= NSEG);
    int seg = gw - side * NSEG;
    const float* dense = side ? uin : iin;
    int s = seg / NUQ;
    int r = seg - s * NUQ;
    int b = g_rp[gw];
    int en = g_rp[gw + 1];
    float4 acc = make_float4(0.f, 0.f, 0.f, 0.f);
    for (int e = b; e < en; e++) {
        int c = g_ecol[e];
        float v = g_eval[e];
        float4 x = __ldg(((const float4*)(dense + (size_t)c * DD)) + lane);
        acc.x += v * x.x;
        acc.y += v * x.y;
        acc.z += v * x.z;
        acc.w += v * x.w;
    }
    acc.x = tf32_rna(acc.x);
    acc.y = tf32_rna(acc.y);
    acc.z = tf32_rna(acc.z);
    acc.w = tf32_rna(acc.w);
    size_t grow = (size_t)(side * NUQ + r);
    ((float4*)(g_P + grow * KTOT + s * DD))[lane] = acc;
}

// ---------------- TF32 tensor-core GEMM + ReLU ------------------------------
//   out[200000,128] = relu( g_P[200000,640] @ g_Wc[640,128] )
// 128x128 block tile, BK=16, 256 threads (8 warps, 64x32 warp tiles),
// double-buffered smem via cp.async, mma.sync.m16n8k8 tf32.
#define BM 128
#define BN 128
#define BK 16
#define ASTRIDE 20    // floats; 80B row stride (16B aligned, conflict-free frags)
#define BSTRIDE 136   // floats; 544B row stride (16B aligned, conflict-free frags)
#define NKIT (KTOT / BK)   // 40

#define CPA(dst, src) asm volatile("cp.async.cg.shared.global [%0], [%1], 16;\n" :: "r"(dst), "l"(src))
#define CPC()         asm volatile("cp.async.commit_group;\n")
#define CPW(n)        asm volatile("cp.async.wait_group %0;\n" :: "n"(n))

#define MMA_TF32(d, a, b)                                                      \
    asm volatile(                                                              \
        "mma.sync.aligned.m16n8k8.row.col.f32.tf32.tf32.f32 "                  \
        "{%0,%1,%2,%3}, {%4,%5,%6,%7}, {%8,%9}, {%0,%1,%2,%3};\n"              \
        : "+f"((d)[0]), "+f"((d)[1]), "+f"((d)[2]), "+f"((d)[3])               \
        : "r"((a)[0]), "r"((a)[1]), "r"((a)[2]), "r"((a)[3]),                  \
          "r"((b)[0]), "r"((b)[1]))

__global__ void __launch_bounds__(256) k_gemm_tc(float* __restrict__ out) {
    __shared__ float As[2][BM * ASTRIDE];
    __shared__ float Bs[2][BK * BSTRIDE];

    int tid = threadIdx.x;
    int wid = tid >> 5, lane = tid & 31;
    int warpm = wid & 1;       // 0..1  (64 rows each)
    int warpn = wid >> 1;      // 0..3  (32 cols each)
    int gid = lane >> 2;       // 0..7
    int tig = lane & 3;        // 0..3
    int mbase = blockIdx.x * BM;

    float c[4][4][4];
#pragma unroll
    for (int mi = 0; mi < 4; mi++)
#pragma unroll
        for (int ni = 0; ni < 4; ni++)
#pragma unroll
            for (int r = 0; r < 4; r++) c[mi][ni][r] = 0.f;

    // A-load chunk mapping (512 16B chunks): chunk -> (row, kchunk)
    int ar0 = tid >> 2, akc0 = (tid & 3) * 4;
    int ar1 = (tid + 256) >> 2, akc1 = akc0;     // (tid+256)&3 == tid&3
    // B-load chunk mapping (512 16B chunks): chunk -> (row, nchunk)
    int br0 = tid >> 5, bnc0 = (tid & 31) * 4;
    int br1 = (tid + 256) >> 5, bnc1 = bnc0;

    long agr0 = min(mbase + ar0, GM - 1);
    long agr1 = min(mbase + ar1, GM - 1);

    const float* Ag0 = g_P + agr0 * KTOT;
    const float* Ag1 = g_P + agr1 * KTOT;

    unsigned sA0[2], sA1[2], sB0[2], sB1[2];
#pragma unroll
    for (int bf = 0; bf < 2; bf++) {
        sA0[bf] = (unsigned)__cvta_generic_to_shared(&As[bf][ar0 * ASTRIDE + akc0]);
        sA1[bf] = (unsigned)__cvta_generic_to_shared(&As[bf][ar1 * ASTRIDE + akc1]);
        sB0[bf] = (unsigned)__cvta_generic_to_shared(&Bs[bf][br0 * BSTRIDE + bnc0]);
        sB1[bf] = (unsigned)__cvta_generic_to_shared(&Bs[bf][br1 * BSTRIDE + bnc1]);
    }

    // prologue: stage 0 into buffer 0
    CPA(sA0[0], Ag0 + 0 * BK + akc0);
    CPA(sA1[0], Ag1 + 0 * BK + akc1);
    CPA(sB0[0], g_Wc + (size_t)(0 * BK + br0) * DD + bnc0);
    CPA(sB1[0], g_Wc + (size_t)(0 * BK + br1) * DD + bnc1);
    CPC();

    for (int kt = 0; kt < NKIT; kt++) {
        int buf = kt & 1;
        if (kt + 1 < NKIT) {
            int nb = buf ^ 1;
            int ktn = kt + 1;
            CPA(sA0[nb], Ag0 + ktn * BK + akc0);
            CPA(sA1[nb], Ag1 + ktn * BK + akc1);
            CPA(sB0[nb], g_Wc + (size_t)(ktn * BK + br0) * DD + bnc0);
            CPA(sB1[nb], g_Wc + (size_t)(ktn * BK + br1) * DD + bnc1);
            CPC();
            CPW(1);
        } else {
            CPW(0);
        }
        __syncthreads();

        const float* Ab = As[buf];
        const float* Bb = Bs[buf];
#pragma unroll
        for (int ks = 0; ks < 2; ks++) {
            int k0 = ks * 8;
            unsigned a[4][4], b[4][2];
#pragma unroll
            for (int mi = 0; mi < 4; mi++) {
                int m = warpm * 64 + mi * 16;
                a[mi][0] = __float_as_uint(Ab[(m + gid) * ASTRIDE + k0 + tig]);
                a[mi][1] = __float_as_uint(Ab[(m + gid + 8) * ASTRIDE + k0 + tig]);
                a[mi][2] = __float_as_uint(Ab[(m + gid) * ASTRIDE + k0 + tig + 4]);
                a[mi][3] = __float_as_uint(Ab[(m + gid + 8) * ASTRIDE + k0 + tig + 4]);
            }
#pragma unroll
            for (int ni = 0; ni < 4; ni++) {
                int n = warpn * 32 + ni * 8 + gid;
                b[ni][0] = __float_as_uint(Bb[(k0 + tig) * BSTRIDE + n]);
                b[ni][1] = __float_as_uint(Bb[(k0 + tig + 4) * BSTRIDE + n]);
            }
#pragma unroll
            for (int mi = 0; mi < 4; mi++)
#pragma unroll
                for (int ni = 0; ni < 4; ni++)
                    MMA_TF32(c[mi][ni], a[mi], b[ni]);
        }
        __syncthreads();
    }

    // epilogue: relu + store (float2 per c-pair)
#pragma unroll
    for (int mi = 0; mi < 4; mi++) {
        int row0 = mbase + warpm * 64 + mi * 16 + gid;
        int row1 = row0 + 8;
#pragma unroll
        for (int ni = 0; ni < 4; ni++) {
            int col = warpn * 32 + ni * 8 + tig * 2;
            if (row0 < GM) {
                float2 v;
                v.x = fmaxf(c[mi][ni][0], 0.f);
                v.y = fmaxf(c[mi][ni][1], 0.f);
                *(float2*)(out + (size_t)row0 * DD + col) = v;
            }
            if (row1 < GM) {
                float2 v;
                v.x = fmaxf(c[mi][ni][2], 0.f);
                v.y = fmaxf(c[mi][ni][3], 0.f);
                *(float2*)(out + (size_t)row1 * DD + col) = v;
            }
        }
    }
}

// ---------------- launcher --------------------------------------------------
extern "C" void kernel_launch(void* const* d_in, const int* in_sizes, int n_in,
                              void* d_out, int out_size) {
    const float* uin   = (const float*)d_in[0];   // user_inputs  [NU,128]
    const float* iin   = (const float*)d_in[1];   // item_inputs  [NI,128]
    const float* w     = (const float*)d_in[2];   // weight       [128,128,5]
    const int*   urows = (const int*)d_in[3];     // u_rows [5,E]
    const int*   ucols = (const int*)d_in[4];
    const float* uvals = (const float*)d_in[5];
    const int*   irows = (const int*)d_in[6];
    const int*   icols = (const int*)d_in[7];
    const float* ivals = (const float*)d_in[8];
    float* out = (float*)d_out;                   // [2*NU*128]: user then item

    (void)in_sizes; (void)n_in; (void)out_size;

    // 1. cumulative weight stack (tf32-rounded)
    k_wc<<<DD, DD>>>(w);

    // 2. CSR build
    k_zero_counts<<<2048, 256>>>();
    k_hist<<<4096, 256>>>(urows, irows);
    int nblk = (TSEG + 1023) / 1024;   // 977
    k_scan1<<<nblk, 1024>>>();
    k_scan2<<<1, 1024>>>(nblk);
    k_scan3<<<nblk, 1024>>>();
    k_scatter<<<4096, 256>>>(urows, ucols, uvals, irows, icols, ivals);

    // 3. SPMM on raw inputs -> P matrix [200000,640] (tf32-rounded)
    int spmm_blocks = (TSEG * 32 + 255) / 256;    // 125000
    k_spmm<<<spmm_blocks, 256>>>(uin, iin);

    // 4. TF32 tensor-core GEMM (K=640) + ReLU -> output
    k_gemm_tc<<<(GM + BM - 1) / BM, 256>>>(out);
}

// round 6
// speedup vs baseline: 2.5743x; 1.3676x over previous
#include <cuda_runtime.h>
#include <cuda_fp16.h>
#include <cstdint>
#include <cstddef>

// Problem constants
#define NUQ 100000
#define NIQ 100000
#define DD 128
#define NSS 5
#define EE 500000
#define NSEG (NSS * NUQ)          // 500000 segments per side
#define NEDGE (NSS * EE)          // 2500000 edges per side
#define KTOT (NSS * DD)           // 640
#define TSEG (2 * NSEG)           // 1000000 total segments
#define TEDGE (2 * NEDGE)         // 5000000 total edges
#define GM (2 * NUQ)              // 200000 GEMM rows (user block then item block)
#define GMPAD (GM + 128)          // padded rows so last-tile loads stay in bounds

// ---------------- static scratch (device globals; no allocation) -----------
__device__ __half g_Wch[KTOT * DD];                  // cumulative weights [640 k][128 n] fp16
__device__ __half g_Ph[(size_t)GMPAD * KTOT];        // P matrix [200128][640] fp16 (pad rows stay 0)
__device__ int    g_cnt[TSEG];                       // per-segment edge counts
__device__ int    g_rp[TSEG + 1];                    // CSR row pointers (joint over both sides)
__device__ int    g_cur[TSEG];                       // scatter cursors
__device__ int2   g_edge[TEDGE];                     // CSR packed (col, val-bits)
__device__ int    g_bsum[1024];                      // scan block sums

// ---------------- cumulative weight stack -----------------------------------
// weight layout: (DIN, DOUT, NS) row-major -> idx = din*DOUT*NS + dout*NS + s
// g_Wch[(s*128 + din)*128 + dout] = fp16( sum_{j<=s} weight[din][dout][j] )
__global__ void k_wc(const float* __restrict__ w) {
    int din = blockIdx.x;     // 128 (k within support)
    int dout = threadIdx.x;   // 128 (n)
    float acc = 0.f;
#pragma unroll
    for (int s = 0; s < NSS; s++) {
        acc += w[din * (DD * NSS) + dout * NSS + s];
        g_Wch[(size_t)(s * DD + din) * DD + dout] = __float2half(acc);
    }
}

// ---------------- CSR build -------------------------------------------------
__global__ void k_zero_counts() {
    for (int i = blockIdx.x * blockDim.x + threadIdx.x; i < TSEG;
         i += gridDim.x * blockDim.x)
        g_cnt[i] = 0;
}

__global__ void k_hist(const int* __restrict__ urows, const int* __restrict__ irows) {
    for (int i = blockIdx.x * blockDim.x + threadIdx.x; i < TEDGE;
         i += gridDim.x * blockDim.x) {
        int side = (i >= NEDGE);
        int e = i - side * NEDGE;
        const int* rows = side ? irows : urows;
        int s = e / EE;
        int r = rows[e];
        atomicAdd(&g_cnt[side * NSEG + s * NUQ + r], 1);
    }
}

__global__ void k_scan1() {
    __shared__ int sh[1024];
    int tid = threadIdx.x;
    int i = blockIdx.x * 1024 + tid;
    int v = (i < TSEG) ? g_cnt[i] : 0;
    sh[tid] = v;
    __syncthreads();
    for (int off = 1; off < 1024; off <<= 1) {
        int t = (tid >= off) ? sh[tid - off] : 0;
        __syncthreads();
        sh[tid] += t;
        __syncthreads();
    }
    if (i < TSEG) g_rp[i] = sh[tid] - v;   // local exclusive
    if (tid == 1023) g_bsum[blockIdx.x] = sh[1023];
}

__global__ void k_scan2(int nb) {
    __shared__ int sh[1024];
    int tid = threadIdx.x;
    int v = (tid < nb) ? g_bsum[tid] : 0;
    sh[tid] = v;
    __syncthreads();
    for (int off = 1; off < 1024; off <<= 1) {
        int t = (tid >= off) ? sh[tid - off] : 0;
        __syncthreads();
        sh[tid] += t;
        __syncthreads();
    }
    if (tid < nb) g_bsum[tid] = sh[tid] - v;  // exclusive block offsets
}

__global__ void k_scan3() {
    int i = blockIdx.x * 1024 + threadIdx.x;
    if (i < TSEG) {
        int v = g_rp[i] + g_bsum[blockIdx.x];
        g_rp[i] = v;
        g_cur[i] = v;
    }
    if (i == 0) g_rp[TSEG] = TEDGE;
}

__global__ void k_scatter(const int* __restrict__ urows, const int* __restrict__ ucols,
                          const float* __restrict__ uvals,
                          const int* __restrict__ irows, const int* __restrict__ icols,
                          const float* __restrict__ ivals) {
    for (int i = blockIdx.x * blockDim.x + threadIdx.x; i < TEDGE;
         i += gridDim.x * blockDim.x) {
        int side = (i >= NEDGE);
        int e = i - side * NEDGE;
        const int* rows = side ? irows : urows;
        const int* cols = side ? icols : ucols;
        const float* vals = side ? ivals : uvals;
        int s = e / EE;
        int seg = side * NSEG + s * NUQ + rows[e];
        int p = atomicAdd(&g_cur[seg], 1);
        g_edge[p] = make_int2(cols[e], __float_as_int(vals[e]));
    }
}

// ---------------- SPMM: one warp per segment --------------------------------
// user side gathers item_inputs, item side gathers user_inputs.
// Writes fp16 to g_Ph so the tensor GEMM reads half traffic.
__global__ void __launch_bounds__(256) k_spmm(const float* __restrict__ uin,
                                              const float* __restrict__ iin) {
    int gw = (blockIdx.x * blockDim.x + threadIdx.x) >> 5;
    int lane = threadIdx.x & 31;
    if (gw >= TSEG) return;
    int side = (gw >= NSEG);
    int seg = gw - side * NSEG;
    const float* dense = side ? uin : iin;
    int s = seg / NUQ;
    int r = seg - s * NUQ;
    int b = g_rp[gw];
    int en = g_rp[gw + 1];
    float4 acc = make_float4(0.f, 0.f, 0.f, 0.f);
    for (int e = b; e < en; e++) {
        int2 ed = __ldg(&g_edge[e]);
        float v = __int_as_float(ed.y);
        float4 x = __ldg(((const float4*)(dense + (size_t)ed.x * DD)) + lane);
        acc.x += v * x.x;
        acc.y += v * x.y;
        acc.z += v * x.z;
        acc.w += v * x.w;
    }
    __half2 h0 = __floats2half2_rn(acc.x, acc.y);
    __half2 h1 = __floats2half2_rn(acc.z, acc.w);
    uint2 st;
    st.x = *(const unsigned*)&h0;
    st.y = *(const unsigned*)&h1;
    size_t grow = (size_t)(side * NUQ + r);
    ((uint2*)(g_Ph + grow * KTOT + s * DD))[lane] = st;
}

// ---------------- FP16 tensor-core GEMM + ReLU ------------------------------
//   out[200000,128] = relu( g_Ph[200000,640] @ g_Wch[640,128] )
// 128x128 block tile, BK=32 (halves), 256 threads (8 warps, 64x32 warp tiles),
// double-buffered cp.async, ldmatrix fragments, mma.sync.m16n8k16.f16.
#define BM 128
#define BK 32
#define ASH 40     // A smem stride in halves (80B rows -> conflict-free LDSM)
#define BSH 136    // B smem stride in halves (272B rows -> conflict-free LDSM)
#define NK (KTOT / BK)   // 20

#define CPA(dst, src) asm volatile("cp.async.cg.shared.global [%0], [%1], 16;\n" :: "r"(dst), "l"(src))
#define CPC()         asm volatile("cp.async.commit_group;\n")
#define CPW(n)        asm volatile("cp.async.wait_group %0;\n" :: "n"(n))

#define LDSM4(r, addr)                                                         \
    asm volatile("ldmatrix.sync.aligned.m8n8.x4.shared.b16 {%0,%1,%2,%3}, [%4];" \
                 : "=r"((r)[0]), "=r"((r)[1]), "=r"((r)[2]), "=r"((r)[3])      \
                 : "r"(addr))
#define LDSM4T(r, addr)                                                        \
    asm volatile("ldmatrix.sync.aligned.m8n8.x4.trans.shared.b16 {%0,%1,%2,%3}, [%4];" \
                 : "=r"((r)[0]), "=r"((r)[1]), "=r"((r)[2]), "=r"((r)[3])      \
                 : "r"(addr))

#define MMA_F16(d, a, b0, b1)                                                  \
    asm volatile(                                                              \
        "mma.sync.aligned.m16n8k16.row.col.f32.f16.f16.f32 "                   \
        "{%0,%1,%2,%3}, {%4,%5,%6,%7}, {%8,%9}, {%0,%1,%2,%3};\n"              \
        : "+f"((d)[0]), "+f"((d)[1]), "+f"((d)[2]), "+f"((d)[3])               \
        : "r"((a)[0]), "r"((a)[1]), "r"((a)[2]), "r"((a)[3]),                  \
          "r"(b0), "r"(b1))

__global__ void __launch_bounds__(256) k_gemm_h(float* __restrict__ out) {
    __shared__ __half As[2][BM * ASH];      // 2 x 10240 B
    __shared__ __half Bs[2][BK * BSH];      // 2 x  8704 B

    int tid = threadIdx.x;
    int wid = tid >> 5, lane = tid & 31;
    int warpm = wid & 1;       // 0..1  (64 rows each)
    int warpn = wid >> 1;      // 0..3  (32 cols each)
    int gid = lane >> 2;       // 0..7
    int tig = lane & 3;        // 0..3
    int mbase = blockIdx.x * BM;

    float c[4][4][4];
#pragma unroll
    for (int mi = 0; mi < 4; mi++)
#pragma unroll
        for (int ni = 0; ni < 4; ni++)
#pragma unroll
            for (int r = 0; r < 4; r++) c[mi][ni][r] = 0.f;

    // cp.async chunk maps (16B = 8 halves per chunk)
    // A: 512 chunks (128 rows x 4); B: 512 chunks (32 k-rows x 16)
    const __half* asrc[2];
    const __half* bsrc[2];
    uint32_t adst[2][2], bdst[2][2];
#pragma unroll
    for (int i = 0; i < 2; i++) {
        int ch = tid + i * 256;
        int ar = ch >> 2, ac = ch & 3;
        asrc[i] = g_Ph + (size_t)(mbase + ar) * KTOT + ac * 8;
        int bk = ch >> 4, bc = ch & 15;
        bsrc[i] = g_Wch + (size_t)bk * DD + bc * 8;
#pragma unroll
        for (int bf = 0; bf < 2; bf++) {
            adst[bf][i] = (uint32_t)__cvta_generic_to_shared(&As[bf][ar * ASH + ac * 8]);
            bdst[bf][i] = (uint32_t)__cvta_generic_to_shared(&Bs[bf][bk * BSH + bc * 8]);
        }
    }

    // ldmatrix per-lane base addresses (bytes)
    uint32_t aAddr[2][4], bAddr[2][2];
    {
        int arow_f = (lane & 15);
        int akk = (lane >> 4) * 8;
        int j = lane >> 3;                       // 0..3
        int brow_f = (j & 1) * 8 + (lane & 7);   // k within 16
        int bn_f = (j >> 1) * 8;                 // n offset within 16
#pragma unroll
        for (int bf = 0; bf < 2; bf++) {
#pragma unroll
            for (int mi = 0; mi < 4; mi++) {
                int row = warpm * 64 + mi * 16 + arow_f;
                aAddr[bf][mi] = (uint32_t)__cvta_generic_to_shared(
                    &As[bf][row * ASH + akk]);
            }
#pragma unroll
            for (int ni2 = 0; ni2 < 2; ni2++) {
                int nn = warpn * 32 + ni2 * 16 + bn_f;
                bAddr[bf][ni2] = (uint32_t)__cvta_generic_to_shared(
                    &Bs[bf][brow_f * BSH + nn]);
            }
        }
    }

    // prologue: stage 0 into buffer 0
#pragma unroll
    for (int i = 0; i < 2; i++) {
        CPA(adst[0][i], asrc[i]);
        CPA(bdst[0][i], bsrc[i]);
    }
    CPC();

    for (int kt = 0; kt < NK; kt++) {
        int buf = kt & 1;
        if (kt + 1 < NK) {
            int nb = buf ^ 1;
            int kh = (kt + 1) * BK;              // half offset into K
#pragma unroll
            for (int i = 0; i < 2; i++) {
                CPA(adst[nb][i], asrc[i] + kh);
                CPA(bdst[nb][i], bsrc[i] + (size_t)kh * DD);
            }
            CPC();
            CPW(1);
        } else {
            CPW(0);
        }
        __syncthreads();

#pragma unroll
        for (int ks = 0; ks < 2; ks++) {
            int k0 = ks * 16;
            uint32_t a[4][4], b[2][4];
#pragma unroll
            for (int mi = 0; mi < 4; mi++)
                LDSM4(a[mi], aAddr[buf][mi] + k0 * 2);
#pragma unroll
            for (int ni2 = 0; ni2 < 2; ni2++)
                LDSM4T(b[ni2], bAddr[buf][ni2] + k0 * (BSH * 2));
#pragma unroll
            for (int mi = 0; mi < 4; mi++)
#pragma unroll
                for (int ni2 = 0; ni2 < 2; ni2++) {
                    MMA_F16(c[mi][ni2 * 2 + 0], a[mi], b[ni2][0], b[ni2][1]);
                    MMA_F16(c[mi][ni2 * 2 + 1], a[mi], b[ni2][2], b[ni2][3]);
                }
        }
        __syncthreads();
    }

    // epilogue: relu + store
#pragma unroll
    for (int mi = 0; mi < 4; mi++) {
        int row0 = mbase + warpm * 64 + mi * 16 + gid;
        int row1 = row0 + 8;
#pragma unroll
        for (int ni = 0; ni < 4; ni++) {
            int col = warpn * 32 + ni * 8 + tig * 2;
            if (row0 < GM) {
                float2 v;
                v.x = fmaxf(c[mi][ni][0], 0.f);
                v.y = fmaxf(c[mi][ni][1], 0.f);
                *(float2*)(out + (size_t)row0 * DD + col) = v;
            }
            if (row1 < GM) {
                float2 v;
                v.x = fmaxf(c[mi][ni][2], 0.f);
                v.y = fmaxf(c[mi][ni][3], 0.f);
                *(float2*)(out + (size_t)row1 * DD + col) = v;
            }
        }
    }
}

// ---------------- launcher --------------------------------------------------
extern "C" void kernel_launch(void* const* d_in, const int* in_sizes, int n_in,
                              void* d_out, int out_size) {
    const float* uin   = (const float*)d_in[0];   // user_inputs  [NU,128]
    const float* iin   = (const float*)d_in[1];   // item_inputs  [NI,128]
    const float* w     = (const float*)d_in[2];   // weight       [128,128,5]
    const int*   urows = (const int*)d_in[3];     // u_rows [5,E]
    const int*   ucols = (const int*)d_in[4];
    const float* uvals = (const float*)d_in[5];
    const int*   irows = (const int*)d_in[6];
    const int*   icols = (const int*)d_in[7];
    const float* ivals = (const float*)d_in[8];
    float* out = (float*)d_out;                   // [2*NU*128]: user then item

    (void)in_sizes; (void)n_in; (void)out_size;

    // 1. cumulative weight stack (fp16)
    k_wc<<<DD, DD>>>(w);

    // 2. CSR build
    k_zero_counts<<<2048, 256>>>();
    k_hist<<<4096, 256>>>(urows, irows);
    int nblk = (TSEG + 1023) / 1024;   // 977
    k_scan1<<<nblk, 1024>>>();
    k_scan2<<<1, 1024>>>(nblk);
    k_scan3<<<nblk, 1024>>>();
    k_scatter<<<4096, 256>>>(urows, ucols, uvals, irows, icols, ivals);

    // 3. SPMM on raw inputs -> P matrix [200000,640] fp16
    int spmm_blocks = (TSEG * 32 + 255) / 256;    // 125000
    k_spmm<<<spmm_blocks, 256>>>(uin, iin);

    // 4. FP16 tensor-core GEMM (K=640) + ReLU -> output
    k_gemm_h<<<(GM + BM - 1) / BM, 256>>>(out);
}

// round 7
// speedup vs baseline: 2.6403x; 1.0256x over previous
#include <cuda_runtime.h>
#include <cuda_fp16.h>
#include <cstdint>
#include <cstddef>

// Problem constants
#define NUQ 100000
#define NIQ 100000
#define DD 128
#define NSS 5
#define EE 500000
#define NSEG (NSS * NUQ)          // 500000 segments per side
#define NEDGE (NSS * EE)          // 2500000 edges per side
#define KTOT (NSS * DD)           // 640
#define TSEG (2 * NSEG)           // 1000000 total segments
#define TEDGE (2 * NEDGE)         // 5000000 total edges
#define GM (2 * NUQ)              // 200000 GEMM rows (user block then item block)
#define GMPAD (GM + 128)          // padded rows so last-tile loads stay in bounds

// ---------------- static scratch (device globals; no allocation) -----------
__device__ __half g_Wch[KTOT * DD];                  // cumulative weights [640 k][128 n] fp16
__device__ __half g_Ph[(size_t)GMPAD * KTOT];        // P matrix [200128][640] fp16 (pad rows stay 0)
__device__ __half g_uh[(size_t)NUQ * DD];            // fp16 copy of user_inputs
__device__ __half g_ih[(size_t)NIQ * DD];            // fp16 copy of item_inputs
__device__ int    g_cnt[TSEG];                       // per-segment edge counts
__device__ int    g_rp[TSEG + 1];                    // CSR row pointers (joint over both sides)
__device__ int    g_cur[TSEG];                       // scatter cursors
__device__ int2   g_edge[TEDGE];                     // CSR packed (col, val-bits)
__device__ int    g_bsum[1024];                      // scan block sums

// ---------------- cumulative weight stack -----------------------------------
// weight layout: (DIN, DOUT, NS) row-major -> idx = din*DOUT*NS + dout*NS + s
// g_Wch[(s*128 + din)*128 + dout] = fp16( sum_{j<=s} weight[din][dout][j] )
__global__ void k_wc(const float* __restrict__ w) {
    int din = blockIdx.x;     // 128 (k within support)
    int dout = threadIdx.x;   // 128 (n)
    float acc = 0.f;
#pragma unroll
    for (int s = 0; s < NSS; s++) {
        acc += w[din * (DD * NSS) + dout * NSS + s];
        g_Wch[(size_t)(s * DD + din) * DD + dout] = __float2half(acc);
    }
}

// ---------------- fp16 copies of dense inputs --------------------------------
__global__ void k_tohalf(const float4* __restrict__ uin, const float4* __restrict__ iin) {
    const int n4 = NUQ * DD / 4;   // 3.2M float4 per side
    for (int i = blockIdx.x * blockDim.x + threadIdx.x; i < 2 * n4;
         i += gridDim.x * blockDim.x) {
        int side = (i >= n4);
        int j = i - side * n4;
        float4 v = side ? iin[j] : uin[j];
        __half2 a = __floats2half2_rn(v.x, v.y);
        __half2 b = __floats2half2_rn(v.z, v.w);
        uint2 st;
        st.x = *(const unsigned*)&a;
        st.y = *(const unsigned*)&b;
        ((uint2*)(side ? g_ih : g_uh))[j] = st;
    }
}

// ---------------- CSR build -------------------------------------------------
__global__ void k_zero_counts() {
    for (int i = blockIdx.x * blockDim.x + threadIdx.x; i < TSEG;
         i += gridDim.x * blockDim.x)
        g_cnt[i] = 0;
}

__global__ void k_hist(const int* __restrict__ urows, const int* __restrict__ irows) {
    for (int i = blockIdx.x * blockDim.x + threadIdx.x; i < TEDGE;
         i += gridDim.x * blockDim.x) {
        int side = (i >= NEDGE);
        int e = i - side * NEDGE;
        const int* rows = side ? irows : urows;
        int s = e / EE;
        int r = rows[e];
        atomicAdd(&g_cnt[side * NSEG + s * NUQ + r], 1);
    }
}

__global__ void k_scan1() {
    __shared__ int sh[1024];
    int tid = threadIdx.x;
    int i = blockIdx.x * 1024 + tid;
    int v = (i < TSEG) ? g_cnt[i] : 0;
    sh[tid] = v;
    __syncthreads();
    for (int off = 1; off < 1024; off <<= 1) {
        int t = (tid >= off) ? sh[tid - off] : 0;
        __syncthreads();
        sh[tid] += t;
        __syncthreads();
    }
    if (i < TSEG) g_rp[i] = sh[tid] - v;   // local exclusive
    if (tid == 1023) g_bsum[blockIdx.x] = sh[1023];
}

__global__ void k_scan2(int nb) {
    __shared__ int sh[1024];
    int tid = threadIdx.x;
    int v = (tid < nb) ? g_bsum[tid] : 0;
    sh[tid] = v;
    __syncthreads();
    for (int off = 1; off < 1024; off <<= 1) {
        int t = (tid >= off) ? sh[tid - off] : 0;
        __syncthreads();
        sh[tid] += t;
        __syncthreads();
    }
    if (tid < nb) g_bsum[tid] = sh[tid] - v;  // exclusive block offsets
}

__global__ void k_scan3() {
    int i = blockIdx.x * 1024 + threadIdx.x;
    if (i < TSEG) {
        int v = g_rp[i] + g_bsum[blockIdx.x];
        g_rp[i] = v;
        g_cur[i] = v;
    }
    if (i == 0) g_rp[TSEG] = TEDGE;
}

__global__ void k_scatter(const int* __restrict__ urows, const int* __restrict__ ucols,
                          const float* __restrict__ uvals,
                          const int* __restrict__ irows, const int* __restrict__ icols,
                          const float* __restrict__ ivals) {
    for (int i = blockIdx.x * blockDim.x + threadIdx.x; i < TEDGE;
         i += gridDim.x * blockDim.x) {
        int side = (i >= NEDGE);
        int e = i - side * NEDGE;
        const int* rows = side ? irows : urows;
        const int* cols = side ? icols : ucols;
        const float* vals = side ? ivals : uvals;
        int s = e / EE;
        int seg = side * NSEG + s * NUQ + rows[e];
        int p = atomicAdd(&g_cur[seg], 1);
        g_edge[p] = make_int2(cols[e], __float_as_int(vals[e]));
    }
}

// ---------------- SPMM: one warp per segment --------------------------------
// user side (side=0) gathers item fp16 rows, item side gathers user fp16 rows.
// fp32 accumulation; writes fp16 to g_Ph.
__global__ void __launch_bounds__(256) k_spmm() {
    int gw = (blockIdx.x * blockDim.x + threadIdx.x) >> 5;
    int lane = threadIdx.x & 31;
    if (gw >= TSEG) return;
    int side = (gw >= NSEG);
    int seg = gw - side * NSEG;
    const __half* dense = side ? g_uh : g_ih;
    int s = seg / NUQ;
    int r = seg - s * NUQ;
    int b = g_rp[gw];
    int en = g_rp[gw + 1];
    float4 acc = make_float4(0.f, 0.f, 0.f, 0.f);
    for (int e = b; e < en; e++) {
        int2 ed = __ldg(&g_edge[e]);
        float v = __int_as_float(ed.y);
        uint2 xh = __ldg(((const uint2*)(dense + (size_t)ed.x * DD)) + lane);
        float2 x0 = __half22float2(*(const __half2*)&xh.x);
        float2 x1 = __half22float2(*(const __half2*)&xh.y);
        acc.x += v * x0.x;
        acc.y += v * x0.y;
        acc.z += v * x1.x;
        acc.w += v * x1.y;
    }
    __half2 h0 = __floats2half2_rn(acc.x, acc.y);
    __half2 h1 = __floats2half2_rn(acc.z, acc.w);
    uint2 st;
    st.x = *(const unsigned*)&h0;
    st.y = *(const unsigned*)&h1;
    size_t grow = (size_t)(side * NUQ + r);
    ((uint2*)(g_Ph + grow * KTOT + s * DD))[lane] = st;
}

// ---------------- FP16 tensor-core GEMM + ReLU ------------------------------
//   out[200000,128] = relu( g_Ph[200000,640] @ g_Wch[640,128] )
// 128x128 block tile, BK=32 (halves), 256 threads (8 warps, 64x32 warp tiles),
// double-buffered cp.async, ldmatrix fragments, mma.sync.m16n8k16.f16.
#define BM 128
#define BK 32
#define ASH 40     // A smem stride in halves (80B rows -> conflict-free LDSM)
#define BSH 136    // B smem stride in halves (272B rows -> conflict-free LDSM)
#define NK (KTOT / BK)   // 20

#define CPA(dst, src) asm volatile("cp.async.cg.shared.global [%0], [%1], 16;\n" :: "r"(dst), "l"(src))
#define CPC()         asm volatile("cp.async.commit_group;\n")
#define CPW(n)        asm volatile("cp.async.wait_group %0;\n" :: "n"(n))

#define LDSM4(r, addr)                                                         \
    asm volatile("ldmatrix.sync.aligned.m8n8.x4.shared.b16 {%0,%1,%2,%3}, [%4];" \
                 : "=r"((r)[0]), "=r"((r)[1]), "=r"((r)[2]), "=r"((r)[3])      \
                 : "r"(addr))
#define LDSM4T(r, addr)                                                        \
    asm volatile("ldmatrix.sync.aligned.m8n8.x4.trans.shared.b16 {%0,%1,%2,%3}, [%4];" \
                 : "=r"((r)[0]), "=r"((r)[1]), "=r"((r)[2]), "=r"((r)[3])      \
                 : "r"(addr))

#define MMA_F16(d, a, b0, b1)                                                  \
    asm volatile(                                                              \
        "mma.sync.aligned.m16n8k16.row.col.f32.f16.f16.f32 "                   \
        "{%0,%1,%2,%3}, {%4,%5,%6,%7}, {%8,%9}, {%0,%1,%2,%3};\n"              \
        : "+f"((d)[0]), "+f"((d)[1]), "+f"((d)[2]), "+f"((d)[3])               \
        : "r"((a)[0]), "r"((a)[1]), "r"((a)[2]), "r"((a)[3]),                  \
          "r"(b0), "r"(b1))

__global__ void __launch_bounds__(256) k_gemm_h(float* __restrict__ out) {
    __shared__ __half As[2][BM * ASH];      // 2 x 10240 B
    __shared__ __half Bs[2][BK * BSH];      // 2 x  8704 B

    int tid = threadIdx.x;
    int wid = tid >> 5, lane = tid & 31;
    int warpm = wid & 1;       // 0..1  (64 rows each)
    int warpn = wid >> 1;      // 0..3  (32 cols each)
    int gid = lane >> 2;       // 0..7
    int tig = lane & 3;        // 0..3
    int mbase = blockIdx.x * BM;

    float c[4][4][4];
#pragma unroll
    for (int mi = 0; mi < 4; mi++)
#pragma unroll
        for (int ni = 0; ni < 4; ni++)
#pragma unroll
            for (int r = 0; r < 4; r++) c[mi][ni][r] = 0.f;

    // cp.async chunk maps (16B = 8 halves per chunk)
    // A: 512 chunks (128 rows x 4); B: 512 chunks (32 k-rows x 16)
    const __half* asrc[2];
    const __half* bsrc[2];
    uint32_t adst[2][2], bdst[2][2];
#pragma unroll
    for (int i = 0; i < 2; i++) {
        int ch = tid + i * 256;
        int ar = ch >> 2, ac = ch & 3;
        asrc[i] = g_Ph + (size_t)(mbase + ar) * KTOT + ac * 8;
        int bk = ch >> 4, bc = ch & 15;
        bsrc[i] = g_Wch + (size_t)bk * DD + bc * 8;
#pragma unroll
        for (int bf = 0; bf < 2; bf++) {
            adst[bf][i] = (uint32_t)__cvta_generic_to_shared(&As[bf][ar * ASH + ac * 8]);
            bdst[bf][i] = (uint32_t)__cvta_generic_to_shared(&Bs[bf][bk * BSH + bc * 8]);
        }
    }

    // ldmatrix per-lane base addresses (bytes)
    uint32_t aAddr[2][4], bAddr[2][2];
    {
        int arow_f = (lane & 15);
        int akk = (lane >> 4) * 8;
        int j = lane >> 3;                       // 0..3
        int brow_f = (j & 1) * 8 + (lane & 7);   // k within 16
        int bn_f = (j >> 1) * 8;                 // n offset within 16
#pragma unroll
        for (int bf = 0; bf < 2; bf++) {
#pragma unroll
            for (int mi = 0; mi < 4; mi++) {
                int row = warpm * 64 + mi * 16 + arow_f;
                aAddr[bf][mi] = (uint32_t)__cvta_generic_to_shared(
                    &As[bf][row * ASH + akk]);
            }
#pragma unroll
            for (int ni2 = 0; ni2 < 2; ni2++) {
                int nn = warpn * 32 + ni2 * 16 + bn_f;
                bAddr[bf][ni2] = (uint32_t)__cvta_generic_to_shared(
                    &Bs[bf][brow_f * BSH + nn]);
            }
        }
    }

    // prologue: stage 0 into buffer 0
#pragma unroll
    for (int i = 0; i < 2; i++) {
        CPA(adst[0][i], asrc[i]);
        CPA(bdst[0][i], bsrc[i]);
    }
    CPC();

    for (int kt = 0; kt < NK; kt++) {
        int buf = kt & 1;
        if (kt + 1 < NK) {
            int nb = buf ^ 1;
            int kh = (kt + 1) * BK;              // half offset into K
#pragma unroll
            for (int i = 0; i < 2; i++) {
                CPA(adst[nb][i], asrc[i] + kh);
                CPA(bdst[nb][i], bsrc[i] + (size_t)kh * DD);
            }
            CPC();
            CPW(1);
        } else {
            CPW(0);
        }
        __syncthreads();

#pragma unroll
        for (int ks = 0; ks < 2; ks++) {
            int k0 = ks * 16;
            uint32_t a[4][4], b[2][4];
#pragma unroll
            for (int mi = 0; mi < 4; mi++)
                LDSM4(a[mi], aAddr[buf][mi] + k0 * 2);
#pragma unroll
            for (int ni2 = 0; ni2 < 2; ni2++)
                LDSM4T(b[ni2], bAddr[buf][ni2] + k0 * (BSH * 2));
#pragma unroll
            for (int mi = 0; mi < 4; mi++)
#pragma unroll
                for (int ni2 = 0; ni2 < 2; ni2++) {
                    MMA_F16(c[mi][ni2 * 2 + 0], a[mi], b[ni2][0], b[ni2][1]);
                    MMA_F16(c[mi][ni2 * 2 + 1], a[mi], b[ni2][2], b[ni2][3]);
                }
        }
        __syncthreads();
    }

    // epilogue: relu + store
#pragma unroll
    for (int mi = 0; mi < 4; mi++) {
        int row0 = mbase + warpm * 64 + mi * 16 + gid;
        int row1 = row0 + 8;
#pragma unroll
        for (int ni = 0; ni < 4; ni++) {
            int col = warpn * 32 + ni * 8 + tig * 2;
            if (row0 < GM) {
                float2 v;
                v.x = fmaxf(c[mi][ni][0], 0.f);
                v.y = fmaxf(c[mi][ni][1], 0.f);
                *(float2*)(out + (size_t)row0 * DD + col) = v;
            }
            if (row1 < GM) {
                float2 v;
                v.x = fmaxf(c[mi][ni][2], 0.f);
                v.y = fmaxf(c[mi][ni][3], 0.f);
                *(float2*)(out + (size_t)row1 * DD + col) = v;
            }
        }
    }
}

// ---------------- launcher --------------------------------------------------
extern "C" void kernel_launch(void* const* d_in, const int* in_sizes, int n_in,
                              void* d_out, int out_size) {
    const float* uin   = (const float*)d_in[0];   // user_inputs  [NU,128]
    const float* iin   = (const float*)d_in[1];   // item_inputs  [NI,128]
    const float* w     = (const float*)d_in[2];   // weight       [128,128,5]
    const int*   urows = (const int*)d_in[3];     // u_rows [5,E]
    const int*   ucols = (const int*)d_in[4];
    const float* uvals = (const float*)d_in[5];
    const int*   irows = (const int*)d_in[6];
    const int*   icols = (const int*)d_in[7];
    const float* ivals = (const float*)d_in[8];
    float* out = (float*)d_out;                   // [2*NU*128]: user then item

    (void)in_sizes; (void)n_in; (void)out_size;

    // 1. cumulative weight stack (fp16) + fp16 input copies
    k_wc<<<DD, DD>>>(w);
    k_tohalf<<<4096, 256>>>((const float4*)uin, (const float4*)iin);

    // 2. CSR build
    k_zero_counts<<<2048, 256>>>();
    k_hist<<<4096, 256>>>(urows, irows);
    int nblk = (TSEG + 1023) / 1024;   // 977
    k_scan1<<<nblk, 1024>>>();
    k_scan2<<<1, 1024>>>(nblk);
    k_scan3<<<nblk, 1024>>>();
    k_scatter<<<4096, 256>>>(urows, ucols, uvals, irows, icols, ivals);

    // 3. SPMM on fp16 inputs -> P matrix [200000,640] fp16
    int spmm_blocks = (TSEG * 32 + 255) / 256;    // 125000
    k_spmm<<<spmm_blocks, 256>>>();

    // 4. FP16 tensor-core GEMM (K=640) + ReLU -> output
    k_gemm_h<<<(GM + BM - 1) / BM, 256>>>(out);
}